// round 14
// baseline (speedup 1.0000x reference)
#include <cuda_runtime.h>
#include <math.h>

#define BATCH 64
#define IMH 512
#define IMW 512
#define NC 64
#define NORI 9
#define NB 63
#define OUT_PER_B (NB*NB*2*2*NORI)   // 142884
#define NPOS (NB*NB)                 // 3969
#define NBOUND 1281                  // boundary positions per image (945 + 336)

// Transposed cell histogram scratch: [B][9][NC][NC] = 9.4 MB (L2-resident)
__device__ float g_hist[(size_t)BATCH * NORI * NC * NC];

__device__ __forceinline__ float fsqrt_approx(float v) {
    float r;
    asm("sqrt.approx.f32 %0, %1;" : "=f"(r) : "f"(v));
    return r;
}

// ---------------------------------------------------------------------------
// Kernel 1: cells (proven R9 structure) + fused INTERIOR block positions.
// Tile = 32x64 px (4x8 cells). After shist is built, threads 0..95 normalize
// the 21 block positions fully interior to this tile (rp%4!=3 && cp%8!=7)
// straight from smem and write them to out. g_hist store kept for the
// boundary kernel.
// ---------------------------------------------------------------------------
__global__ __launch_bounds__(256, 5) void hog_cells_kernel(const float* __restrict__ x,
                                                           float* __restrict__ out)
{
    __shared__ float sm[34][68];        // 34x66 gray halo tile, padded stride
    __shared__ float shist[NORI][32];   // per-cell hist staging

    const int bx = blockIdx.x;          // 0..7   (64-px cols)
    const int by = blockIdx.y;          // 0..15  (32-px rows)
    const int b  = blockIdx.z;
    const int tid = threadIdx.x;
    const int oy = by * 32;
    const int ox = bx * 64;

    // ---- interior 32x64 gray: 2x (3x LDG.128 -> 4 pixels) ----
    const int row0 = tid >> 4;              // 0..15
    const int g0   = tid & 15;
    const size_t offA = ((size_t)((b * IMH) + oy + row0) * IMW + ox + g0 * 4) * 3;
    const size_t offB = ((size_t)((b * IMH) + oy + row0 + 16) * IMW + ox + g0 * 4) * 3;
    const float4* pA = reinterpret_cast<const float4*>(x + offA);
    const float4* pB = reinterpret_cast<const float4*>(x + offB);

    // ---- halo ring (196 px): unconditional load, predicated store ----
    const int ht = (tid < 196) ? tid : 195;
    int lr, lc;
    if (ht < 66)       { lr = 0;        lc = ht;       }
    else if (ht < 132) { lr = 33;       lc = ht - 66;  }
    else if (ht < 164) { lr = ht - 131; lc = 0;        }
    else               { lr = ht - 163; lc = 65;       }
    int hh = oy - 1 + lr;
    int hw = ox - 1 + lc;
    hh = (hh < 0) ? 1 : ((hh > IMH - 1) ? IMH - 2 : hh);
    hw = (hw < 0) ? 1 : ((hw > IMW - 1) ? IMW - 2 : hw);
    const float* hp = x + ((size_t)(b * IMH + hh) * IMW + hw) * 3;

    // issue all loads back-to-back
    const float4 a0 = pA[0], a1 = pA[1], a2 = pA[2];
    const float4 b0 = pB[0], b1 = pB[1], b2 = pB[2];
    const float  h0 = hp[0], h1 = hp[1], h2 = hp[2];

    {
        float* d = &sm[row0 + 1][g0 * 4 + 1];
        d[0] = 0.2125f * a0.x + 0.7154f * a0.y + 0.0721f * a0.z;
        d[1] = 0.2125f * a0.w + 0.7154f * a1.x + 0.0721f * a1.y;
        d[2] = 0.2125f * a1.z + 0.7154f * a1.w + 0.0721f * a2.x;
        d[3] = 0.2125f * a2.y + 0.7154f * a2.z + 0.0721f * a2.w;
        float* e = &sm[row0 + 17][g0 * 4 + 1];
        e[0] = 0.2125f * b0.x + 0.7154f * b0.y + 0.0721f * b0.z;
        e[1] = 0.2125f * b0.w + 0.7154f * b1.x + 0.0721f * b1.y;
        e[2] = 0.2125f * b1.z + 0.7154f * b1.w + 0.0721f * b2.x;
        e[3] = 0.2125f * b2.y + 0.7154f * b2.z + 0.0721f * b2.w;
    }
    if (tid < 196)
        sm[lr][lc] = 0.2125f * h0 + 0.7154f * h1 + 0.0721f * h2;
    __syncthreads();

    // ---- 2x4 pixel patch per thread (8 threads per 8x8 cell) ----
    const int cell = tid >> 3;          // 0..31
    const int sub  = tid & 7;
    const int py0 = (cell >> 3) * 8 + (sub >> 1) * 2;
    const int px0 = (cell & 7) * 8 + (sub & 1) * 4;

    float P[4][6];
#pragma unroll
    for (int r = 0; r < 4; r++) {
        const float4 a = *reinterpret_cast<const float4*>(&sm[py0 + r][px0]);
        const float2 e = *reinterpret_cast<const float2*>(&sm[py0 + r][px0 + 4]);
        P[r][0] = a.x; P[r][1] = a.y; P[r][2] = a.z; P[r][3] = a.w;
        P[r][4] = e.x; P[r][5] = e.y;
    }

    float c[NORI];
#pragma unroll
    for (int o = 0; o < NORI; o++) c[o] = 0.0f;

#pragma unroll
    for (int dy = 0; dy < 2; dy++) {
#pragma unroll
        for (int dx = 0; dx < 4; dx++) {
            const float gr = P[dy + 2][dx + 1] - P[dy][dx + 1];
            const float gc = P[dy + 1][dx + 2] - P[dy + 1][dx];
            const float mag = fsqrt_approx(gr * gr + gc * gc);

            const bool flip = (gr < 0.0f) || (gr == 0.0f && gc < 0.0f);
            const float yy = flip ? -gr : gr;
            const float xx = flip ? -gc : gc;

            const float xa1 = xx * 0.3420201433f;
            const float xa2 = xx * 0.6427876097f;
            const float xa3 = xx * 0.8660254038f;
            const float xa4 = xx * 0.9848077530f;
            const float s1 = xa1 - yy * 0.9396926208f;
            const float s8 = xa1 + yy * 0.9396926208f;
            const float s2 = xa2 - yy * 0.7660444431f;
            const float s7 = xa2 + yy * 0.7660444431f;
            const float s3 = xa3 - yy * 0.5000000000f;
            const float s6 = xa3 + yy * 0.5000000000f;
            const float s4 = xa4 - yy * 0.1736481777f;
            const float s5 = xa4 + yy * 0.1736481777f;

            c[0] += mag;
            if (s1 < 0.0f) c[1] += mag;
            if (s2 < 0.0f) c[2] += mag;
            if (s3 < 0.0f) c[3] += mag;
            if (s4 < 0.0f) c[4] += mag;
            if (s5 < 0.0f) c[5] += mag;
            if (s6 < 0.0f) c[6] += mag;
            if (s7 < 0.0f) c[7] += mag;
            if (s8 < 0.0f) c[8] += mag;
        }
    }

#pragma unroll
    for (int o = 0; o < NORI; o++) {
        c[o] += __shfl_xor_sync(0xffffffffu, c[o], 1);
        c[o] += __shfl_xor_sync(0xffffffffu, c[o], 2);
        c[o] += __shfl_xor_sync(0xffffffffu, c[o], 4);
    }

    if (sub == 0) {
#pragma unroll
        for (int o = 0; o < NORI - 1; o++)
            shist[o][cell] = (c[o] - c[o + 1]) * 0.015625f;
        shist[NORI - 1][cell] = c[NORI - 1] * 0.015625f;
    }
    __syncthreads();

    // ---- fused INTERIOR block positions (21 per tile, 4 threads each) ----
    // warps 0..2 (96 threads); groups of 4 lanes never mix real/dummy
    // (84 = 21*4; lanes 84..95 are whole dummy groups).
    if (tid < 96) {
        const int lpr = (tid >> 2 < 21) ? (tid >> 2) : 20;   // clamped position
        const int q   = tid & 3;
        const int rpl = lpr / 7;            // 0..2
        const int cpl = lpr - rpl * 7;      // 0..6
        const int ci  = (rpl + (q >> 1)) * 8 + (cpl + (q & 1));

        const float v0 = shist[0][ci];
        const float v1 = shist[1][ci];
        const float v2 = shist[2][ci];
        const float v3 = shist[3][ci];
        const float v4 = shist[4][ci];
        const float v5 = shist[5][ci];
        const float v6 = shist[6][ci];
        const float v7 = shist[7][ci];
        const float v8 = shist[8][ci];

        float ss = 0.25e-10f;
        ss = fmaf(v0, v0, ss); ss = fmaf(v1, v1, ss); ss = fmaf(v2, v2, ss);
        ss = fmaf(v3, v3, ss); ss = fmaf(v4, v4, ss); ss = fmaf(v5, v5, ss);
        ss = fmaf(v6, v6, ss); ss = fmaf(v7, v7, ss); ss = fmaf(v8, v8, ss);
        ss += __shfl_xor_sync(0xffffffffu, ss, 1);
        ss += __shfl_xor_sync(0xffffffffu, ss, 2);

        const float n1 = rsqrtf(ss);
        const float w0 = fminf(v0 * n1, 0.2f);
        const float w1 = fminf(v1 * n1, 0.2f);
        const float w2 = fminf(v2 * n1, 0.2f);
        const float w3 = fminf(v3 * n1, 0.2f);
        const float w4 = fminf(v4 * n1, 0.2f);
        const float w5 = fminf(v5 * n1, 0.2f);
        const float w6 = fminf(v6 * n1, 0.2f);
        const float w7 = fminf(v7 * n1, 0.2f);
        const float w8 = fminf(v8 * n1, 0.2f);

        float ss2 = 0.25e-10f;
        ss2 = fmaf(w0, w0, ss2); ss2 = fmaf(w1, w1, ss2); ss2 = fmaf(w2, w2, ss2);
        ss2 = fmaf(w3, w3, ss2); ss2 = fmaf(w4, w4, ss2); ss2 = fmaf(w5, w5, ss2);
        ss2 = fmaf(w6, w6, ss2); ss2 = fmaf(w7, w7, ss2); ss2 = fmaf(w8, w8, ss2);
        ss2 += __shfl_xor_sync(0xffffffffu, ss2, 1);
        ss2 += __shfl_xor_sync(0xffffffffu, ss2, 2);

        const float n2 = rsqrtf(ss2);
        if (tid < 84) {
            const int rp = by * 4 + rpl;    // rp%4 != 3 by construction
            const int cp = bx * 8 + cpl;    // cp%8 != 7 by construction
            float* d = out + (size_t)b * OUT_PER_B + ((size_t)rp * NB + cp) * 36 + q * NORI;
            d[0] = w0 * n2; d[1] = w1 * n2; d[2] = w2 * n2;
            d[3] = w3 * n2; d[4] = w4 * n2; d[5] = w5 * n2;
            d[6] = w6 * n2; d[7] = w7 * n2; d[8] = w8 * n2;
        }
    }

    // ---- transposed global store: g_hist[b][o][cellY][cellX] ----
    const size_t base = (size_t)b * NORI * NC * NC;
    for (int i = tid; i < NORI * 32; i += 256) {
        const int o   = i >> 5;
        const int cl  = i & 31;
        g_hist[base + (size_t)o * (NC * NC) + (by * 4 + (cl >> 3)) * NC + (bx * 8 + (cl & 7))]
            = shist[o][cl];
    }
}

// ---------------------------------------------------------------------------
// Kernel 2: BOUNDARY positions only (rp%4==3 or cp%8==7), enumerated
// analytically so all lanes are uniformly active. 1281 positions per image.
//   slot s < 945 : rp = (s/63)*4+3, cp = s%63           (rows straddling)
//   else t=s-945 : cp = (t/48)*8+7, rp = r0 + r0/3       (cols straddling,
//                  r0 = t%48 maps to rp !≡ 3 mod 4)
// ---------------------------------------------------------------------------
__global__ __launch_bounds__(256) void hog_boundary_kernel(float* __restrict__ out)
{
    const int b   = blockIdx.y;
    const int s0  = blockIdx.x * 64;
    const int tid = threadIdx.x;

    const int lp = tid >> 2;
    const int q  = tid & 3;
    const int s  = s0 + lp;
    const bool valid = (s < NBOUND);
    const int sc = valid ? s : NBOUND - 1;

    int rp, cp;
    if (sc < 945) {
        const int rr = sc / 63;
        rp = rr * 4 + 3;
        cp = sc - rr * 63;
    } else {
        const int t  = sc - 945;
        const int cq = t / 48;
        cp = cq * 8 + 7;
        const int r0 = t - cq * 48;
        rp = r0 + r0 / 3;
    }

    const int dr = q >> 1;
    const int dc = q & 1;
    const float* hp = g_hist + (size_t)b * NORI * NC * NC + (rp + dr) * NC + (cp + dc);

    const float v0 = hp[0 * 4096];
    const float v1 = hp[1 * 4096];
    const float v2 = hp[2 * 4096];
    const float v3 = hp[3 * 4096];
    const float v4 = hp[4 * 4096];
    const float v5 = hp[5 * 4096];
    const float v6 = hp[6 * 4096];
    const float v7 = hp[7 * 4096];
    const float v8 = hp[8 * 4096];

    float ss = 0.25e-10f;
    ss = fmaf(v0, v0, ss); ss = fmaf(v1, v1, ss); ss = fmaf(v2, v2, ss);
    ss = fmaf(v3, v3, ss); ss = fmaf(v4, v4, ss); ss = fmaf(v5, v5, ss);
    ss = fmaf(v6, v6, ss); ss = fmaf(v7, v7, ss); ss = fmaf(v8, v8, ss);
    ss += __shfl_xor_sync(0xffffffffu, ss, 1);
    ss += __shfl_xor_sync(0xffffffffu, ss, 2);

    const float n1 = rsqrtf(ss);
    const float w0 = fminf(v0 * n1, 0.2f);
    const float w1 = fminf(v1 * n1, 0.2f);
    const float w2 = fminf(v2 * n1, 0.2f);
    const float w3 = fminf(v3 * n1, 0.2f);
    const float w4 = fminf(v4 * n1, 0.2f);
    const float w5 = fminf(v5 * n1, 0.2f);
    const float w6 = fminf(v6 * n1, 0.2f);
    const float w7 = fminf(v7 * n1, 0.2f);
    const float w8 = fminf(v8 * n1, 0.2f);

    float ss2 = 0.25e-10f;
    ss2 = fmaf(w0, w0, ss2); ss2 = fmaf(w1, w1, ss2); ss2 = fmaf(w2, w2, ss2);
    ss2 = fmaf(w3, w3, ss2); ss2 = fmaf(w4, w4, ss2); ss2 = fmaf(w5, w5, ss2);
    ss2 = fmaf(w6, w6, ss2); ss2 = fmaf(w7, w7, ss2); ss2 = fmaf(w8, w8, ss2);
    ss2 += __shfl_xor_sync(0xffffffffu, ss2, 1);
    ss2 += __shfl_xor_sync(0xffffffffu, ss2, 2);

    const float n2 = rsqrtf(ss2);
    if (valid) {
        float* d = out + (size_t)b * OUT_PER_B + ((size_t)rp * NB + cp) * 36 + q * NORI;
        d[0] = w0 * n2; d[1] = w1 * n2; d[2] = w2 * n2;
        d[3] = w3 * n2; d[4] = w4 * n2; d[5] = w5 * n2;
        d[6] = w6 * n2; d[7] = w7 * n2; d[8] = w8 * n2;
    }
}

extern "C" void kernel_launch(void* const* d_in, const int* in_sizes, int n_in,
                              void* d_out, int out_size)
{
    const float* x = (const float*)d_in[0];
    float* out = (float*)d_out;

    dim3 g1(IMW / 64, IMH / 32, BATCH);          // (8, 16, 64) = 8192 CTAs
    hog_cells_kernel<<<g1, 256>>>(x, out);

    dim3 g2((NBOUND + 63) / 64, BATCH);          // (21, 64)
    hog_boundary_kernel<<<g2, 256>>>(out);
}

// round 15
// speedup vs baseline: 1.0567x; 1.0567x over previous
#include <cuda_runtime.h>
#include <math.h>

#define BATCH 64
#define IMH 512
#define IMW 512
#define NC 64
#define NORI 9
#define NB 63
#define OUT_PER_B (NB*NB*2*2*NORI)   // 142884
#define NPOS (NB*NB)                 // 3969

// Transposed cell histogram scratch: [B][9][NC][NC] = 9.4 MB (L2-resident)
__device__ float g_hist[(size_t)BATCH * NORI * NC * NC];

__device__ __forceinline__ float fsqrt_approx(float v) {
    float r;
    asm("sqrt.approx.f32 %0, %1;" : "=f"(r) : "f"(v));
    return r;
}

// ---------------------------------------------------------------------------
// Kernel 1: gray -> gradients -> orientation cumsum -> 8x8 cell histograms
// (byte-identical to the proven 61.9us R9 version)
// ---------------------------------------------------------------------------
__global__ __launch_bounds__(256, 5) void hog_cells_kernel(const float* __restrict__ x)
{
    __shared__ float sm[34][68];        // 34x66 gray halo tile, padded stride
    __shared__ float shist[NORI][32];   // per-cell hist staging

    const int bx = blockIdx.x;          // 0..7   (64-px cols)
    const int by = blockIdx.y;          // 0..15  (32-px rows)
    const int b  = blockIdx.z;
    const int tid = threadIdx.x;
    const int oy = by * 32;
    const int ox = bx * 64;

    // ---- interior 32x64 gray: 2x (3x LDG.128 -> 4 pixels) ----
    const int row0 = tid >> 4;              // 0..15
    const int g0   = tid & 15;
    const size_t offA = ((size_t)((b * IMH) + oy + row0) * IMW + ox + g0 * 4) * 3;
    const size_t offB = ((size_t)((b * IMH) + oy + row0 + 16) * IMW + ox + g0 * 4) * 3;
    const float4* pA = reinterpret_cast<const float4*>(x + offA);
    const float4* pB = reinterpret_cast<const float4*>(x + offB);

    // ---- halo ring (196 px): unconditional load, predicated store ----
    const int ht = (tid < 196) ? tid : 195;
    int lr, lc;
    if (ht < 66)       { lr = 0;        lc = ht;       }
    else if (ht < 132) { lr = 33;       lc = ht - 66;  }
    else if (ht < 164) { lr = ht - 131; lc = 0;        }
    else               { lr = ht - 163; lc = 65;       }
    int hh = oy - 1 + lr;
    int hw = ox - 1 + lc;
    hh = (hh < 0) ? 1 : ((hh > IMH - 1) ? IMH - 2 : hh);
    hw = (hw < 0) ? 1 : ((hw > IMW - 1) ? IMW - 2 : hw);
    const float* hp = x + ((size_t)(b * IMH + hh) * IMW + hw) * 3;

    // issue all loads back-to-back
    const float4 a0 = pA[0], a1 = pA[1], a2 = pA[2];
    const float4 b0 = pB[0], b1 = pB[1], b2 = pB[2];
    const float  h0 = hp[0], h1 = hp[1], h2 = hp[2];

    {
        float* d = &sm[row0 + 1][g0 * 4 + 1];
        d[0] = 0.2125f * a0.x + 0.7154f * a0.y + 0.0721f * a0.z;
        d[1] = 0.2125f * a0.w + 0.7154f * a1.x + 0.0721f * a1.y;
        d[2] = 0.2125f * a1.z + 0.7154f * a1.w + 0.0721f * a2.x;
        d[3] = 0.2125f * a2.y + 0.7154f * a2.z + 0.0721f * a2.w;
        float* e = &sm[row0 + 17][g0 * 4 + 1];
        e[0] = 0.2125f * b0.x + 0.7154f * b0.y + 0.0721f * b0.z;
        e[1] = 0.2125f * b0.w + 0.7154f * b1.x + 0.0721f * b1.y;
        e[2] = 0.2125f * b1.z + 0.7154f * b1.w + 0.0721f * b2.x;
        e[3] = 0.2125f * b2.y + 0.7154f * b2.z + 0.0721f * b2.w;
    }
    if (tid < 196)
        sm[lr][lc] = 0.2125f * h0 + 0.7154f * h1 + 0.0721f * h2;
    __syncthreads();

    // ---- 2x4 pixel patch per thread (8 threads per 8x8 cell) ----
    const int cell = tid >> 3;
    const int sub  = tid & 7;
    const int py0 = (cell >> 3) * 8 + (sub >> 1) * 2;
    const int px0 = (cell & 7) * 8 + (sub & 1) * 4;

    float P[4][6];
#pragma unroll
    for (int r = 0; r < 4; r++) {
        const float4 a = *reinterpret_cast<const float4*>(&sm[py0 + r][px0]);
        const float2 e = *reinterpret_cast<const float2*>(&sm[py0 + r][px0 + 4]);
        P[r][0] = a.x; P[r][1] = a.y; P[r][2] = a.z; P[r][3] = a.w;
        P[r][4] = e.x; P[r][5] = e.y;
    }

    float c[NORI];
#pragma unroll
    for (int o = 0; o < NORI; o++) c[o] = 0.0f;

#pragma unroll
    for (int dy = 0; dy < 2; dy++) {
#pragma unroll
        for (int dx = 0; dx < 4; dx++) {
            const float gr = P[dy + 2][dx + 1] - P[dy][dx + 1];
            const float gc = P[dy + 1][dx + 2] - P[dy + 1][dx];
            const float mag = fsqrt_approx(gr * gr + gc * gc);

            const bool flip = (gr < 0.0f) || (gr == 0.0f && gc < 0.0f);
            const float yy = flip ? -gr : gr;
            const float xx = flip ? -gc : gc;

            const float xa1 = xx * 0.3420201433f;
            const float xa2 = xx * 0.6427876097f;
            const float xa3 = xx * 0.8660254038f;
            const float xa4 = xx * 0.9848077530f;
            const float s1 = xa1 - yy * 0.9396926208f;
            const float s8 = xa1 + yy * 0.9396926208f;
            const float s2 = xa2 - yy * 0.7660444431f;
            const float s7 = xa2 + yy * 0.7660444431f;
            const float s3 = xa3 - yy * 0.5000000000f;
            const float s6 = xa3 + yy * 0.5000000000f;
            const float s4 = xa4 - yy * 0.1736481777f;
            const float s5 = xa4 + yy * 0.1736481777f;

            c[0] += mag;
            if (s1 < 0.0f) c[1] += mag;
            if (s2 < 0.0f) c[2] += mag;
            if (s3 < 0.0f) c[3] += mag;
            if (s4 < 0.0f) c[4] += mag;
            if (s5 < 0.0f) c[5] += mag;
            if (s6 < 0.0f) c[6] += mag;
            if (s7 < 0.0f) c[7] += mag;
            if (s8 < 0.0f) c[8] += mag;
        }
    }

#pragma unroll
    for (int o = 0; o < NORI; o++) {
        c[o] += __shfl_xor_sync(0xffffffffu, c[o], 1);
        c[o] += __shfl_xor_sync(0xffffffffu, c[o], 2);
        c[o] += __shfl_xor_sync(0xffffffffu, c[o], 4);
    }

    if (sub == 0) {
#pragma unroll
        for (int o = 0; o < NORI - 1; o++)
            shist[o][cell] = (c[o] - c[o + 1]) * 0.015625f;
        shist[NORI - 1][cell] = c[NORI - 1] * 0.015625f;
    }
    __syncthreads();

    // ---- transposed global store: g_hist[b][o][cellY][cellX] ----
    const size_t base = (size_t)b * NORI * NC * NC;
    for (int i = tid; i < NORI * 32; i += 256) {
        const int o   = i >> 5;
        const int cl  = i & 31;
        g_hist[base + (size_t)o * (NC * NC) + (by * 4 + (cl >> 3)) * NC + (bx * 8 + (cl & 7))]
            = shist[o][cl];
    }
}

// ---------------------------------------------------------------------------
// Kernel 2: ROW-TILED blocks. CTA = one row of 63 block positions.
// Stage cell rows {rp, rp+1} x 64 cols x 9 planes (1152 floats) in smem via
// perfectly coalesced segment loads; 2x2 gathers become LDS; contiguous
// float4 output. Same 4032-CTA latency-hiding volume as the proven version.
// ---------------------------------------------------------------------------
#define SEG_PAD 66
__global__ __launch_bounds__(256) void hog_blocks_kernel(float* __restrict__ out)
{
    __shared__ float ct[18 * SEG_PAD];   // 18 segments (o,dr) of 64 cols, padded
    __shared__ float buf[63 * 36];       // staged output row (9072 B)

    const int rp  = blockIdx.x;          // 0..62
    const int b   = blockIdx.y;
    const int tid = threadIdx.x;

    // ---- Phase A: coalesced load of 18 x 64-float segments ----
    const size_t base = (size_t)b * NORI * NC * NC + (size_t)rp * NC;
    for (int i = tid; i < 18 * 64; i += 256) {
        const int seg = i >> 6;          // o*2 + dr
        const int col = i & 63;
        const int o   = seg >> 1;
        const int dr  = seg & 1;
        ct[seg * SEG_PAD + col] = g_hist[base + (size_t)o * (NC * NC) + dr * NC + col];
    }
    __syncthreads();

    // ---- Phase B: 4 threads per position, cells read from smem ----
    const int lp = tid >> 2;             // 0..63 (63 = dummy)
    const int q  = tid & 3;
    const bool valid = (lp < NB);
    const int cp = valid ? lp : NB - 1;
    const int dr = q >> 1;
    const int dc = q & 1;

    const float* cbase = &ct[dr * SEG_PAD + cp + dc];
    const float v0 = cbase[0 * 2 * SEG_PAD];
    const float v1 = cbase[1 * 2 * SEG_PAD];
    const float v2 = cbase[2 * 2 * SEG_PAD];
    const float v3 = cbase[3 * 2 * SEG_PAD];
    const float v4 = cbase[4 * 2 * SEG_PAD];
    const float v5 = cbase[5 * 2 * SEG_PAD];
    const float v6 = cbase[6 * 2 * SEG_PAD];
    const float v7 = cbase[7 * 2 * SEG_PAD];
    const float v8 = cbase[8 * 2 * SEG_PAD];

    float ss = 0.25e-10f;                // EPS^2 split across 4 lanes
    ss = fmaf(v0, v0, ss); ss = fmaf(v1, v1, ss); ss = fmaf(v2, v2, ss);
    ss = fmaf(v3, v3, ss); ss = fmaf(v4, v4, ss); ss = fmaf(v5, v5, ss);
    ss = fmaf(v6, v6, ss); ss = fmaf(v7, v7, ss); ss = fmaf(v8, v8, ss);
    ss += __shfl_xor_sync(0xffffffffu, ss, 1);
    ss += __shfl_xor_sync(0xffffffffu, ss, 2);

    const float n1 = rsqrtf(ss);
    const float w0 = fminf(v0 * n1, 0.2f);
    const float w1 = fminf(v1 * n1, 0.2f);
    const float w2 = fminf(v2 * n1, 0.2f);
    const float w3 = fminf(v3 * n1, 0.2f);
    const float w4 = fminf(v4 * n1, 0.2f);
    const float w5 = fminf(v5 * n1, 0.2f);
    const float w6 = fminf(v6 * n1, 0.2f);
    const float w7 = fminf(v7 * n1, 0.2f);
    const float w8 = fminf(v8 * n1, 0.2f);

    float ss2 = 0.25e-10f;
    ss2 = fmaf(w0, w0, ss2); ss2 = fmaf(w1, w1, ss2); ss2 = fmaf(w2, w2, ss2);
    ss2 = fmaf(w3, w3, ss2); ss2 = fmaf(w4, w4, ss2); ss2 = fmaf(w5, w5, ss2);
    ss2 = fmaf(w6, w6, ss2); ss2 = fmaf(w7, w7, ss2); ss2 = fmaf(w8, w8, ss2);
    ss2 += __shfl_xor_sync(0xffffffffu, ss2, 1);
    ss2 += __shfl_xor_sync(0xffffffffu, ss2, 2);

    const float n2 = rsqrtf(ss2);
    if (valid) {
        float* d = &buf[lp * 36 + q * NORI];
        d[0] = w0 * n2; d[1] = w1 * n2; d[2] = w2 * n2;
        d[3] = w3 * n2; d[4] = w4 * n2; d[5] = w5 * n2;
        d[6] = w6 * n2; d[7] = w7 * n2; d[8] = w8 * n2;
    }
    __syncthreads();

    // ---- Phase C: contiguous coalesced float4 copy-out (63*36 = 2268 floats) ----
    const float4* s4 = reinterpret_cast<const float4*>(buf);
    float4* o4 = reinterpret_cast<float4*>(out + (size_t)b * OUT_PER_B + (size_t)rp * NB * 36);
    for (int i = tid; i < 63 * 9; i += 256)
        o4[i] = s4[i];
}

extern "C" void kernel_launch(void* const* d_in, const int* in_sizes, int n_in,
                              void* d_out, int out_size)
{
    const float* x = (const float*)d_in[0];
    float* out = (float*)d_out;

    dim3 g1(IMW / 64, IMH / 32, BATCH);          // (8, 16, 64) = 8192 CTAs
    hog_cells_kernel<<<g1, 256>>>(x);

    dim3 g2(NB, BATCH);                          // (63, 64) = 4032 CTAs
    hog_blocks_kernel<<<g2, 256>>>(out);
}

// round 17
// speedup vs baseline: 1.2084x; 1.1435x over previous
#include <cuda_runtime.h>
#include <math.h>

#define BATCH 64
#define IMH 512
#define IMW 512
#define NC 64
#define NORI 9
#define NB 63
#define OUT_PER_B (NB*NB*2*2*NORI)   // 142884
#define NPOS (NB*NB)                 // 3969

// Transposed cell histogram scratch: [B][9][NC][NC] = 9.4 MB (L2-resident)
__device__ float g_hist[(size_t)BATCH * NORI * NC * NC];

__device__ __forceinline__ float fsqrt_approx(float v) {
    float r;
    asm("sqrt.approx.f32 %0, %1;" : "=f"(r) : "f"(v));
    return r;
}

// ---------------------------------------------------------------------------
// Kernel 1: gray -> gradients -> orientation cumsum -> 8x8 cell histograms
// (proven R9 structure; x reads are __ldcs streaming loads: x is used exactly
//  once, so evict-first keeps g_hist L2-resident for kernel 2)
// ---------------------------------------------------------------------------
__global__ __launch_bounds__(256, 5) void hog_cells_kernel(const float* __restrict__ x)
{
    __shared__ float sm[34][68];        // 34x66 gray halo tile, padded stride
    __shared__ float shist[NORI][32];   // per-cell hist staging

    const int bx = blockIdx.x;          // 0..7   (64-px cols)
    const int by = blockIdx.y;          // 0..15  (32-px rows)
    const int b  = blockIdx.z;
    const int tid = threadIdx.x;
    const int oy = by * 32;
    const int ox = bx * 64;

    // ---- interior 32x64 gray: 2x (3x LDG.128 -> 4 pixels) ----
    const int row0 = tid >> 4;              // 0..15
    const int g0   = tid & 15;
    const size_t offA = ((size_t)((b * IMH) + oy + row0) * IMW + ox + g0 * 4) * 3;
    const size_t offB = ((size_t)((b * IMH) + oy + row0 + 16) * IMW + ox + g0 * 4) * 3;
    const float4* pA = reinterpret_cast<const float4*>(x + offA);
    const float4* pB = reinterpret_cast<const float4*>(x + offB);

    // ---- halo ring (196 px): unconditional load, predicated store ----
    const int ht = (tid < 196) ? tid : 195;
    int lr, lc;
    if (ht < 66)       { lr = 0;        lc = ht;       }
    else if (ht < 132) { lr = 33;       lc = ht - 66;  }
    else if (ht < 164) { lr = ht - 131; lc = 0;        }
    else               { lr = ht - 163; lc = 65;       }
    int hh = oy - 1 + lr;
    int hw = ox - 1 + lc;
    hh = (hh < 0) ? 1 : ((hh > IMH - 1) ? IMH - 2 : hh);
    hw = (hw < 0) ? 1 : ((hw > IMW - 1) ? IMW - 2 : hw);
    const float* hp = x + ((size_t)(b * IMH + hh) * IMW + hw) * 3;

    // issue all loads back-to-back (streaming: evict-first)
    const float4 a0 = __ldcs(pA + 0), a1 = __ldcs(pA + 1), a2 = __ldcs(pA + 2);
    const float4 b0 = __ldcs(pB + 0), b1 = __ldcs(pB + 1), b2 = __ldcs(pB + 2);
    const float  h0 = __ldcs(hp + 0), h1 = __ldcs(hp + 1), h2 = __ldcs(hp + 2);

    {
        float* d = &sm[row0 + 1][g0 * 4 + 1];
        d[0] = 0.2125f * a0.x + 0.7154f * a0.y + 0.0721f * a0.z;
        d[1] = 0.2125f * a0.w + 0.7154f * a1.x + 0.0721f * a1.y;
        d[2] = 0.2125f * a1.z + 0.7154f * a1.w + 0.0721f * a2.x;
        d[3] = 0.2125f * a2.y + 0.7154f * a2.z + 0.0721f * a2.w;
        float* e = &sm[row0 + 17][g0 * 4 + 1];
        e[0] = 0.2125f * b0.x + 0.7154f * b0.y + 0.0721f * b0.z;
        e[1] = 0.2125f * b0.w + 0.7154f * b1.x + 0.0721f * b1.y;
        e[2] = 0.2125f * b1.z + 0.7154f * b1.w + 0.0721f * b2.x;
        e[3] = 0.2125f * b2.y + 0.7154f * b2.z + 0.0721f * b2.w;
    }
    if (tid < 196)
        sm[lr][lc] = 0.2125f * h0 + 0.7154f * h1 + 0.0721f * h2;
    __syncthreads();

    // ---- 2x4 pixel patch per thread (8 threads per 8x8 cell) ----
    const int cell = tid >> 3;
    const int sub  = tid & 7;
    const int py0 = (cell >> 3) * 8 + (sub >> 1) * 2;
    const int px0 = (cell & 7) * 8 + (sub & 1) * 4;

    float P[4][6];
#pragma unroll
    for (int r = 0; r < 4; r++) {
        const float4 a = *reinterpret_cast<const float4*>(&sm[py0 + r][px0]);
        const float2 e = *reinterpret_cast<const float2*>(&sm[py0 + r][px0 + 4]);
        P[r][0] = a.x; P[r][1] = a.y; P[r][2] = a.z; P[r][3] = a.w;
        P[r][4] = e.x; P[r][5] = e.y;
    }

    float c[NORI];
#pragma unroll
    for (int o = 0; o < NORI; o++) c[o] = 0.0f;

#pragma unroll
    for (int dy = 0; dy < 2; dy++) {
#pragma unroll
        for (int dx = 0; dx < 4; dx++) {
            const float gr = P[dy + 2][dx + 1] - P[dy][dx + 1];
            const float gc = P[dy + 1][dx + 2] - P[dy + 1][dx];
            const float mag = fsqrt_approx(gr * gr + gc * gc);

            const bool flip = (gr < 0.0f) || (gr == 0.0f && gc < 0.0f);
            const float yy = flip ? -gr : gr;
            const float xx = flip ? -gc : gc;

            const float xa1 = xx * 0.3420201433f;
            const float xa2 = xx * 0.6427876097f;
            const float xa3 = xx * 0.8660254038f;
            const float xa4 = xx * 0.9848077530f;
            const float s1 = xa1 - yy * 0.9396926208f;
            const float s8 = xa1 + yy * 0.9396926208f;
            const float s2 = xa2 - yy * 0.7660444431f;
            const float s7 = xa2 + yy * 0.7660444431f;
            const float s3 = xa3 - yy * 0.5000000000f;
            const float s6 = xa3 + yy * 0.5000000000f;
            const float s4 = xa4 - yy * 0.1736481777f;
            const float s5 = xa4 + yy * 0.1736481777f;

            c[0] += mag;
            if (s1 < 0.0f) c[1] += mag;
            if (s2 < 0.0f) c[2] += mag;
            if (s3 < 0.0f) c[3] += mag;
            if (s4 < 0.0f) c[4] += mag;
            if (s5 < 0.0f) c[5] += mag;
            if (s6 < 0.0f) c[6] += mag;
            if (s7 < 0.0f) c[7] += mag;
            if (s8 < 0.0f) c[8] += mag;
        }
    }

#pragma unroll
    for (int o = 0; o < NORI; o++) {
        c[o] += __shfl_xor_sync(0xffffffffu, c[o], 1);
        c[o] += __shfl_xor_sync(0xffffffffu, c[o], 2);
        c[o] += __shfl_xor_sync(0xffffffffu, c[o], 4);
    }

    if (sub == 0) {
#pragma unroll
        for (int o = 0; o < NORI - 1; o++)
            shist[o][cell] = (c[o] - c[o + 1]) * 0.015625f;
        shist[NORI - 1][cell] = c[NORI - 1] * 0.015625f;
    }
    __syncthreads();

    // ---- transposed global store: g_hist[b][o][cellY][cellX] ----
    const size_t base = (size_t)b * NORI * NC * NC;
    for (int i = tid; i < NORI * 32; i += 256) {
        const int o   = i >> 5;
        const int cl  = i & 31;
        g_hist[base + (size_t)o * (NC * NC) + (by * 4 + (cl >> 3)) * NC + (bx * 8 + (cl & 7))]
            = shist[o][cl];
    }
}

// ---------------------------------------------------------------------------
// Kernel 2: 4 threads per block position, array-free scalars, shfl-reduced
// norms, conflict-free smem staging, float4 coalesced out.
// (byte-identical to the proven 11.6us R10 version)
// ---------------------------------------------------------------------------
__global__ __launch_bounds__(256) void hog_blocks_kernel(float* __restrict__ out)
{
    __shared__ float buf[64 * 36];

    const int b   = blockIdx.y;
    const int p0  = blockIdx.x * 64;
    const int tid = threadIdx.x;

    const int lp = tid >> 2;
    const int q  = tid & 3;
    const int p  = p0 + lp;
    const bool valid = (p < NPOS);
    const int pc = valid ? p : NPOS - 1;
    const int rp = pc / NB;
    const int cp = pc - rp * NB;
    const int dr = q >> 1;
    const int dc = q & 1;

    const float* hp = g_hist + (size_t)b * NORI * NC * NC + (rp + dr) * NC + (cp + dc);

    const float v0 = hp[0 * 4096];
    const float v1 = hp[1 * 4096];
    const float v2 = hp[2 * 4096];
    const float v3 = hp[3 * 4096];
    const float v4 = hp[4 * 4096];
    const float v5 = hp[5 * 4096];
    const float v6 = hp[6 * 4096];
    const float v7 = hp[7 * 4096];
    const float v8 = hp[8 * 4096];

    float ss = 0.25e-10f;
    ss = fmaf(v0, v0, ss); ss = fmaf(v1, v1, ss); ss = fmaf(v2, v2, ss);
    ss = fmaf(v3, v3, ss); ss = fmaf(v4, v4, ss); ss = fmaf(v5, v5, ss);
    ss = fmaf(v6, v6, ss); ss = fmaf(v7, v7, ss); ss = fmaf(v8, v8, ss);
    ss += __shfl_xor_sync(0xffffffffu, ss, 1);
    ss += __shfl_xor_sync(0xffffffffu, ss, 2);

    const float n1 = rsqrtf(ss);
    const float w0 = fminf(v0 * n1, 0.2f);
    const float w1 = fminf(v1 * n1, 0.2f);
    const float w2 = fminf(v2 * n1, 0.2f);
    const float w3 = fminf(v3 * n1, 0.2f);
    const float w4 = fminf(v4 * n1, 0.2f);
    const float w5 = fminf(v5 * n1, 0.2f);
    const float w6 = fminf(v6 * n1, 0.2f);
    const float w7 = fminf(v7 * n1, 0.2f);
    const float w8 = fminf(v8 * n1, 0.2f);

    float ss2 = 0.25e-10f;
    ss2 = fmaf(w0, w0, ss2); ss2 = fmaf(w1, w1, ss2); ss2 = fmaf(w2, w2, ss2);
    ss2 = fmaf(w3, w3, ss2); ss2 = fmaf(w4, w4, ss2); ss2 = fmaf(w5, w5, ss2);
    ss2 = fmaf(w6, w6, ss2); ss2 = fmaf(w7, w7, ss2); ss2 = fmaf(w8, w8, ss2);
    ss2 += __shfl_xor_sync(0xffffffffu, ss2, 1);
    ss2 += __shfl_xor_sync(0xffffffffu, ss2, 2);

    const float n2 = rsqrtf(ss2);
    if (valid) {
        float* d = &buf[lp * 36 + q * NORI];
        d[0] = w0 * n2; d[1] = w1 * n2; d[2] = w2 * n2;
        d[3] = w3 * n2; d[4] = w4 * n2; d[5] = w5 * n2;
        d[6] = w6 * n2; d[7] = w7 * n2; d[8] = w8 * n2;
    }
    __syncthreads();

    const int npos = min(64, NPOS - p0);
    const int n4 = npos * 9;
    const float4* s4 = reinterpret_cast<const float4*>(buf);
    float4* o4 = reinterpret_cast<float4*>(out + (size_t)b * OUT_PER_B + (size_t)p0 * 36);
    for (int i = tid; i < n4; i += 256)
        o4[i] = s4[i];
}

extern "C" void kernel_launch(void* const* d_in, const int* in_sizes, int n_in,
                              void* d_out, int out_size)
{
    const float* x = (const float*)d_in[0];
    float* out = (float*)d_out;

    dim3 g1(IMW / 64, IMH / 32, BATCH);          // (8, 16, 64) = 8192 CTAs
    hog_cells_kernel<<<g1, 256>>>(x);

    dim3 g2((NPOS + 63) / 64, BATCH);            // (63, 64)
    hog_blocks_kernel<<<g2, 256>>>(out);
}